// round 5
// baseline (speedup 1.0000x reference)
#include <cuda_runtime.h>
#include <cuda_bf16.h>

#define VOCAB  32000
#define NLABEL 16
#define NSTATE 64
#define BATCH  512
#define MAXLEN 512

typedef unsigned long long ull;

// Packed f32x2 ops (sm_103a; SASS FFMA2 — PTX-only path).
#define FMA2(d, a, b, c) \
    asm("fma.rn.f32x2 %0, %1, %2, %3;" : "=l"(d) : "l"(a), "l"(b), "l"(c))
#define ADD2(d, a, b) \
    asm("add.rn.f32x2 %0, %1, %2;" : "=l"(d) : "l"(a), "l"(b))

// Precomputed tables (device globals: no allocation allowed).
// g_Tpack float layout: Texp[r][i] stored at (i>>1)*128 + r*2 + (i&1).
// As 8-byte pairs: ull index jv*64 + r = (Texp[r][2jv], Texp[r][2jv+1]).
__device__ __align__(16) float g_Tpack[NSTATE * NSTATE];
__device__ float g_Oexp[NLABEL * NSTATE];   // [l*64 + s] = softmax(output[l,:])[s]
__device__ float g_lse [VOCAB];             // logsumexp(emb[v,:])

// ---------------------------------------------------------------------------
// Fused prep: blocks [0,40) do row-softmax (2 rows/block: 64+16 rows total);
// blocks [40, 40+VOCAB/4) do per-vocab-row logsumexp (4 rows/block).
// ---------------------------------------------------------------------------
__global__ void prep_all_kernel(const float* __restrict__ transition,
                                const float* __restrict__ output,
                                const float* __restrict__ emb) {
    const int blk = blockIdx.x;
    if (blk < 40) {
        const int half = threadIdx.x >> 6;     // which row in this block
        const int i    = threadIdx.x & 63;     // state index within row
        const int r    = blk * 2 + half;       // global row 0..79
        const float* src = (r < NSTATE) ? (transition + r * NSTATE)
                                        : (output + (r - NSTATE) * NSTATE);
        float v = src[i];

        __shared__ float shm[4];
        __shared__ float shs[4];

        float m = v;
        #pragma unroll
        for (int d = 16; d; d >>= 1) m = fmaxf(m, __shfl_xor_sync(0xffffffffu, m, d));
        if ((threadIdx.x & 31) == 0) shm[threadIdx.x >> 5] = m;
        __syncthreads();
        m = fmaxf(shm[half * 2], shm[half * 2 + 1]);

        float e = expf(v - m);
        float s = e;
        #pragma unroll
        for (int d = 16; d; d >>= 1) s += __shfl_xor_sync(0xffffffffu, s, d);
        if ((threadIdx.x & 31) == 0) shs[threadIdx.x >> 5] = s;
        __syncthreads();
        s = shs[half * 2] + shs[half * 2 + 1];

        const float val = e / s;
        if (r < NSTATE) g_Tpack[(i >> 1) * 128 + r * 2 + (i & 1)] = val;
        else            g_Oexp[(r - NSTATE) * NSTATE + i] = val;
    } else {
        const int gw   = (blk - 40) * 4 + (threadIdx.x >> 5);
        const int lane = threadIdx.x & 31;
        if (gw >= VOCAB) return;
        const float* row = emb + gw * NSTATE;
        float s = expf(row[lane]) + expf(row[lane + 32]);
        #pragma unroll
        for (int d = 16; d; d >>= 1) s += __shfl_xor_sync(0xffffffffu, s, d);
        if (lane == 0) g_lse[gw] = logf(s);
    }
}

// ---------------------------------------------------------------------------
// Main: ONE WARP per batch element. Lane l owns states 2l and 2l+1.
// R3-proven skeleton: in-loop __syncwarp, SMEM token staging, 3-deep emission
// prefetch, unnormalized recurrence. New: FMA2 ordered for operand-reuse
// (g.x / g.y consumers adjacent), static double buffers with unroll-2,
// next-step exp computed in the post-STS gap, renorm every 64 steps via shfl.
// ---------------------------------------------------------------------------
__global__ void __launch_bounds__(32) hmm_forward_kernel(
    const int*   __restrict__ sentences,
    const int*   __restrict__ length,
    const float* __restrict__ emb,
    float*       __restrict__ out)
{
    const int b    = blockIdx.x;
    const int lane = threadIdx.x;

    __shared__ __align__(16) float G0[NSTATE];
    __shared__ __align__(16) float G1[NSTATE];
    __shared__ int toks[MAXLEN];

    const int  L    = length[b];
    const int  Lm1  = L - 1;
    const int* sent = sentences + b * MAXLEN;

    // Stage tokens in SMEM (coalesced, <=16 iterations).
    for (int i = lane; i < L; i += 32) toks[i] = __ldg(&sent[i]);

    // Transition rows for states 2*lane, 2*lane+1 in 64 packed f32x2 pairs.
    ull TA[NSTATE / 2], TB[NSTATE / 2];
    {
        const ulonglong2* Tp = reinterpret_cast<const ulonglong2*>(g_Tpack);
        #pragma unroll
        for (int jv = 0; jv < NSTATE / 2; ++jv) {
            const ulonglong2 p = __ldg(&Tp[jv * 32 + lane]);
            TA[jv] = p.x;
            TB[jv] = p.y;
        }
    }

    // ---- t = 0 + prologue prefetch (clamped indices: always-valid loads) ----
    const int    tok0 = __ldg(&sent[0]);
    const float2 raw0 = *reinterpret_cast<const float2*>(&emb[tok0 * NSTATE + 2 * lane]);
    float2 rA = *reinterpret_cast<const float2*>(&emb[toks[min(1, Lm1)] * NSTATE + 2 * lane]);
    float2 rB = *reinterpret_cast<const float2*>(&emb[toks[min(2, Lm1)] * NSTATE + 2 * lane]);
    float2 rC = *reinterpret_cast<const float2*>(&emb[toks[min(3, Lm1)] * NSTATE + 2 * lane]);

    *reinterpret_cast<float2*>(&G0[2 * lane]) =
        make_float2(__expf(raw0.x), __expf(raw0.y));
    float eA = __expf(rA.x);           // emission factors for step t=1
    float eB = __expf(rA.y);
    __syncwarp();                      // staging + G0 visible warp-wide

    float off = 0.f;
    int   t   = 1;

    // One recurrence step: SRC -> DST, consuming (eA,eB), refilling them for
    // the next step in the gap after the STS. Matvec ordered so both
    // consumers of g.x (then g.y) are adjacent -> ptxas .reuse drops a bank
    // read on the second FFMA2 of each pair.
#define HMM_STEP(SRC, DST)                                                     \
    {                                                                          \
        const ulonglong2* Gv = reinterpret_cast<const ulonglong2*>(SRC);       \
        ull a0 = 0ull, a1 = 0ull, b0 = 0ull, b1 = 0ull;                        \
        _Pragma("unroll")                                                      \
        for (int jv = 0; jv < 16; ++jv) {                                      \
            const ulonglong2 g = Gv[jv];                                       \
            FMA2(a0, TA[2 * jv + 0], g.x, a0);                                 \
            FMA2(b0, TB[2 * jv + 0], g.x, b0);                                 \
            FMA2(a1, TA[2 * jv + 1], g.y, a1);                                 \
            FMA2(b1, TB[2 * jv + 1], g.y, b1);                                 \
        }                                                                      \
        ull as, bs;                                                            \
        ADD2(as, a0, a1);                                                      \
        ADD2(bs, b0, b1);                                                      \
        float alo, ahi, blo, bhi;                                              \
        asm("mov.b64 {%0, %1}, %2;" : "=f"(alo), "=f"(ahi) : "l"(as));         \
        asm("mov.b64 {%0, %1}, %2;" : "=f"(blo), "=f"(bhi) : "l"(bs));         \
        const float GnA = (alo + ahi) * eA;                                    \
        const float GnB = (blo + bhi) * eB;                                    \
        *reinterpret_cast<float2*>(&(DST)[2 * lane]) = make_float2(GnA, GnB);  \
        /* gap work: exp for step t+1, rotate prefetch, issue LDG for t+3 */   \
        eA = __expf(rB.x);                                                     \
        eB = __expf(rB.y);                                                     \
        rB = rC;                                                               \
        rC = *reinterpret_cast<const float2*>(                                 \
                 &emb[toks[min(t + 3, Lm1)] * NSTATE + 2 * lane]);             \
        if (((t + 1) & 63) == 0 && t + 1 < L) {   /* uniform, rare */          \
            const float g0 = __shfl_sync(0xffffffffu, GnA, 0);                 \
            float c;                                                           \
            asm("rcp.approx.f32 %0, %1;" : "=f"(c) : "f"(g0));                 \
            eA *= c;                                                           \
            eB *= c;                                                           \
            off += __logf(g0);                                                 \
        }                                                                      \
        __syncwarp();                                                          \
        ++t;                                                                   \
    }

    while (t + 1 < L) {          // pairs of steps with static buffers
        HMM_STEP(G0, G1)
        HMM_STEP(G1, G0)
    }
    const float* Gf = G0;
    if (t < L) {                 // odd remaining step
        HMM_STEP(G0, G1)
        Gf = G1;
    }
#undef HMM_STEP

    // ---- emission-normalizer sum S = sum_{t<L} lse[tok_t] ----
    float S = 0.f;
    for (int i = lane; i < L; i += 32) S += __ldg(&g_lse[toks[i]]);
    #pragma unroll
    for (int d = 16; d; d >>= 1) S += __shfl_xor_sync(0xffffffffu, S, d);

    // ---- readout: lanes 0..15 each compute one label ----
    if (lane < NLABEL) {
        const float* O = g_Oexp + lane * NSTATE;
        float a0 = 0.f, a1 = 0.f, a2 = 0.f, a3 = 0.f;
        #pragma unroll
        for (int j4 = 0; j4 < NSTATE / 4; ++j4) {
            a0 = fmaf(__ldg(&O[4 * j4 + 0]), Gf[4 * j4 + 0], a0);
            a1 = fmaf(__ldg(&O[4 * j4 + 1]), Gf[4 * j4 + 1], a1);
            a2 = fmaf(__ldg(&O[4 * j4 + 2]), Gf[4 * j4 + 2], a2);
            a3 = fmaf(__ldg(&O[4 * j4 + 3]), Gf[4 * j4 + 3], a3);
        }
        out[b * NLABEL + lane] = __logf((a0 + a1) + (a2 + a3)) + off - S;
    }
}

// ---------------------------------------------------------------------------
extern "C" void kernel_launch(void* const* d_in, const int* in_sizes, int n_in,
                              void* d_out, int out_size) {
    const int*   sentences  = nullptr;
    const int*   length     = nullptr;
    const float* emb        = nullptr;
    const float* transition = nullptr;
    const float* output     = nullptr;

    for (int i = 0; i < n_in; ++i) {
        switch (in_sizes[i]) {
            case BATCH * MAXLEN:   sentences  = (const int*)  d_in[i]; break;
            case BATCH:            length     = (const int*)  d_in[i]; break;
            case VOCAB * NSTATE:   emb        = (const float*)d_in[i]; break;
            case NSTATE * NSTATE:  transition = (const float*)d_in[i]; break;
            case NLABEL * NSTATE:  output     = (const float*)d_in[i]; break;
            default: break;
        }
    }

    prep_all_kernel<<<40 + VOCAB / 4, 128>>>(transition, output, emb);
    hmm_forward_kernel<<<BATCH, 32>>>(sentences, length, emb, (float*)d_out);
}

// round 6
// speedup vs baseline: 1.3098x; 1.3098x over previous
#include <cuda_runtime.h>
#include <cuda_bf16.h>

#define VOCAB  32000
#define NLABEL 16
#define NSTATE 64
#define BATCH  512
#define MAXLEN 512

typedef unsigned long long ull;

// Packed f32x2 ops (sm_103a; SASS FFMA2 — PTX-only path).
#define FMA2(d, a, b, c) \
    asm("fma.rn.f32x2 %0, %1, %2, %3;" : "=l"(d) : "l"(a), "l"(b), "l"(c))
#define ADD2(d, a, b) \
    asm("add.rn.f32x2 %0, %1, %2;" : "=l"(d) : "l"(a), "l"(b))

// Precomputed tables (device globals: no allocation allowed).
// g_Tpack float layout: Texp[r][i] stored at (i>>1)*128 + r*2 + (i&1).
// As 8-byte pairs: ull index jv*64 + r = (Texp[r][2jv], Texp[r][2jv+1]).
__device__ __align__(16) float g_Tpack[NSTATE * NSTATE];
__device__ float g_Oexp[NLABEL * NSTATE];   // [l*64 + s] = softmax(output[l,:])[s]
__device__ float g_lse [VOCAB];             // logsumexp(emb[v,:])

// ---------------------------------------------------------------------------
// Fused prep: blocks [0,40) do row-softmax (2 rows/block: 64+16 rows total);
// blocks [40, 40+VOCAB/4) do per-vocab-row logsumexp (4 rows/block).
// ---------------------------------------------------------------------------
__global__ void prep_all_kernel(const float* __restrict__ transition,
                                const float* __restrict__ output,
                                const float* __restrict__ emb) {
    const int blk = blockIdx.x;
    if (blk < 40) {
        const int half = threadIdx.x >> 6;     // which row in this block
        const int i    = threadIdx.x & 63;     // state index within row
        const int r    = blk * 2 + half;       // global row 0..79
        const float* src = (r < NSTATE) ? (transition + r * NSTATE)
                                        : (output + (r - NSTATE) * NSTATE);
        float v = src[i];

        __shared__ float shm[4];
        __shared__ float shs[4];

        float m = v;
        #pragma unroll
        for (int d = 16; d; d >>= 1) m = fmaxf(m, __shfl_xor_sync(0xffffffffu, m, d));
        if ((threadIdx.x & 31) == 0) shm[threadIdx.x >> 5] = m;
        __syncthreads();
        m = fmaxf(shm[half * 2], shm[half * 2 + 1]);

        float e = expf(v - m);
        float s = e;
        #pragma unroll
        for (int d = 16; d; d >>= 1) s += __shfl_xor_sync(0xffffffffu, s, d);
        if ((threadIdx.x & 31) == 0) shs[threadIdx.x >> 5] = s;
        __syncthreads();
        s = shs[half * 2] + shs[half * 2 + 1];

        const float val = e / s;
        if (r < NSTATE) g_Tpack[(i >> 1) * 128 + r * 2 + (i & 1)] = val;
        else            g_Oexp[(r - NSTATE) * NSTATE + i] = val;
    } else {
        const int gw   = (blk - 40) * 4 + (threadIdx.x >> 5);
        const int lane = threadIdx.x & 31;
        if (gw >= VOCAB) return;
        const float* row = emb + gw * NSTATE;
        float s = expf(row[lane]) + expf(row[lane + 32]);
        #pragma unroll
        for (int d = 16; d; d >>= 1) s += __shfl_xor_sync(0xffffffffu, s, d);
        if (lane == 0) g_lse[gw] = logf(s);
    }
}

// ---------------------------------------------------------------------------
// Main: ONE WARP per batch element. Lane l owns states 2l and 2l+1.
// EXACT R3 loop structure (measured ~90us forward pass): warp-synchronous,
// in-loop __syncwarp, dynamic double-buffer index, exp at loop top, 3-deep
// emission prefetch, FMA2 order a0,a1,b0,b1. Only delta vs R3: renorm period
// 16 -> 64 (same uniform branch, 4x rarer).
// ---------------------------------------------------------------------------
__global__ void __launch_bounds__(32) hmm_forward_kernel(
    const int*   __restrict__ sentences,
    const int*   __restrict__ length,
    const float* __restrict__ emb,
    float*       __restrict__ out)
{
    const int b    = blockIdx.x;
    const int lane = threadIdx.x;

    __shared__ __align__(16) float G[2][NSTATE];
    __shared__ int toks[MAXLEN];

    const int  L    = length[b];
    const int  Lm1  = L - 1;
    const int* sent = sentences + b * MAXLEN;

    // Stage tokens in SMEM (coalesced, 16 iterations max).
    for (int i = lane; i < L; i += 32) toks[i] = __ldg(&sent[i]);

    // Transition rows for states s0=2*lane, s1=2*lane+1:
    // TA[jv] = (Texp[s0][2jv], Texp[s0][2jv+1]), TB likewise for s1.
    // One LDG.128 per jv (16B per lane, coalesced).
    ull TA[NSTATE / 2], TB[NSTATE / 2];
    {
        const ulonglong2* Tp = reinterpret_cast<const ulonglong2*>(g_Tpack);
        #pragma unroll
        for (int jv = 0; jv < NSTATE / 2; ++jv) {
            const ulonglong2 p = __ldg(&Tp[jv * 32 + lane]);   // ull idx jv*64+2l
            TA[jv] = p.x;
            TB[jv] = p.y;
        }
    }

    // ---- t = 0 ----
    const int tok0 = __ldg(&sent[0]);
    const float2 raw0 = *reinterpret_cast<const float2*>(&emb[tok0 * NSTATE + 2 * lane]);
    *reinterpret_cast<float2*>(&G[0][2 * lane]) =
        make_float2(__expf(raw0.x), __expf(raw0.y));
    __syncwarp();   // G[0] + toks visible warp-wide

    // 3-deep emission-row prefetch (clamped indices: always valid loads).
    float2 r1 = *reinterpret_cast<const float2*>(&emb[toks[min(1, Lm1)] * NSTATE + 2 * lane]);
    float2 r2 = *reinterpret_cast<const float2*>(&emb[toks[min(2, Lm1)] * NSTATE + 2 * lane]);
    float2 r3 = *reinterpret_cast<const float2*>(&emb[toks[min(3, Lm1)] * NSTATE + 2 * lane]);

    float off = 0.f;
    int   buf = 0;

    for (int t = 1; t < L; ++t) {
        float eA = __expf(r1.x);
        float eB = __expf(r1.y);
        r1 = r2; r2 = r3;
        r3 = *reinterpret_cast<const float2*>(&emb[toks[min(t + 3, Lm1)] * NSTATE + 2 * lane]);

        if ((t & 63) == 0) {       // periodic renormalization (uniform branch)
            const float g0 = G[buf][0];
            float c;
            asm("rcp.approx.f32 %0, %1;" : "=f"(c) : "f"(g0));
            eA *= c;
            eB *= c;
            off += __logf(g0);
        }

        // Two 64-wide matvecs (states s0, s1) from shared G, packed f32x2.
        const ulonglong2* Gv = reinterpret_cast<const ulonglong2*>(G[buf]);
        ull a0 = 0ull, a1 = 0ull, b0 = 0ull, b1 = 0ull;
        #pragma unroll
        for (int jv = 0; jv < 16; ++jv) {
            const ulonglong2 g = Gv[jv];
            FMA2(a0, TA[2 * jv + 0], g.x, a0);
            FMA2(a1, TA[2 * jv + 1], g.y, a1);
            FMA2(b0, TB[2 * jv + 0], g.x, b0);
            FMA2(b1, TB[2 * jv + 1], g.y, b1);
        }
        ull as, bs;
        ADD2(as, a0, a1);
        ADD2(bs, b0, b1);
        float alo, ahi, blo, bhi;
        asm("mov.b64 {%0, %1}, %2;" : "=f"(alo), "=f"(ahi) : "l"(as));
        asm("mov.b64 {%0, %1}, %2;" : "=f"(blo), "=f"(bhi) : "l"(bs));
        const float GnA = (alo + ahi) * eA;
        const float GnB = (blo + bhi) * eB;

        buf ^= 1;
        *reinterpret_cast<float2*>(&G[buf][2 * lane]) = make_float2(GnA, GnB);
        __syncwarp();
    }

    // ---- emission-normalizer sum S = sum_{t<L} lse[tok_t] ----
    float S = 0.f;
    for (int i = lane; i < L; i += 32) S += __ldg(&g_lse[toks[i]]);
    #pragma unroll
    for (int d = 16; d; d >>= 1) S += __shfl_xor_sync(0xffffffffu, S, d);

    // ---- readout: lanes 0..15 each compute one label ----
    if (lane < NLABEL) {
        const float* O  = g_Oexp + lane * NSTATE;
        const float* Gf = G[buf];
        float a0 = 0.f, a1 = 0.f, a2 = 0.f, a3 = 0.f;
        #pragma unroll
        for (int j4 = 0; j4 < NSTATE / 4; ++j4) {
            a0 = fmaf(__ldg(&O[4 * j4 + 0]), Gf[4 * j4 + 0], a0);
            a1 = fmaf(__ldg(&O[4 * j4 + 1]), Gf[4 * j4 + 1], a1);
            a2 = fmaf(__ldg(&O[4 * j4 + 2]), Gf[4 * j4 + 2], a2);
            a3 = fmaf(__ldg(&O[4 * j4 + 3]), Gf[4 * j4 + 3], a3);
        }
        out[b * NLABEL + lane] = __logf((a0 + a1) + (a2 + a3)) + off - S;
    }
}

// ---------------------------------------------------------------------------
extern "C" void kernel_launch(void* const* d_in, const int* in_sizes, int n_in,
                              void* d_out, int out_size) {
    const int*   sentences  = nullptr;
    const int*   length     = nullptr;
    const float* emb        = nullptr;
    const float* transition = nullptr;
    const float* output     = nullptr;

    for (int i = 0; i < n_in; ++i) {
        switch (in_sizes[i]) {
            case BATCH * MAXLEN:   sentences  = (const int*)  d_in[i]; break;
            case BATCH:            length     = (const int*)  d_in[i]; break;
            case VOCAB * NSTATE:   emb        = (const float*)d_in[i]; break;
            case NSTATE * NSTATE:  transition = (const float*)d_in[i]; break;
            case NLABEL * NSTATE:  output     = (const float*)d_in[i]; break;
            default: break;
        }
    }

    prep_all_kernel<<<40 + VOCAB / 4, 128>>>(transition, output, emb);
    hmm_forward_kernel<<<BATCH, 32>>>(sentences, length, emb, (float*)d_out);
}

// round 7
// speedup vs baseline: 1.3133x; 1.0026x over previous
#include <cuda_runtime.h>
#include <cuda_bf16.h>

#define VOCAB  32000
#define NLABEL 16
#define NSTATE 64
#define BATCH  512
#define MAXLEN 512

typedef unsigned long long ull;

// Packed f32x2 ops (sm_103a; SASS FFMA2 — PTX-only path).
#define FMA2(d, a, b, c) \
    asm("fma.rn.f32x2 %0, %1, %2, %3;" : "=l"(d) : "l"(a), "l"(b), "l"(c))
#define ADD2(d, a, b) \
    asm("add.rn.f32x2 %0, %1, %2;" : "=l"(d) : "l"(a), "l"(b))

// Precomputed tables (device globals: no allocation allowed).
// g_Tpack float layout: Texp[r][i] stored at (i>>1)*128 + r*2 + (i&1).
// As 8-byte pairs: ull index jv*64 + r = (Texp[r][2jv], Texp[r][2jv+1]).
__device__ __align__(16) float g_Tpack[NSTATE * NSTATE];
__device__ float g_Oexp[NLABEL * NSTATE];   // [l*64 + s] = softmax(output[l,:])[s]
__device__ float g_lse [VOCAB];             // logsumexp(emb[v,:])

// ---------------------------------------------------------------------------
// Fused prep: blocks [0,40) do row-softmax (2 rows/block: 64+16 rows total);
// blocks [40, 40+VOCAB/4) do per-vocab-row logsumexp (4 rows/block).
// ---------------------------------------------------------------------------
__global__ void prep_all_kernel(const float* __restrict__ transition,
                                const float* __restrict__ output,
                                const float* __restrict__ emb) {
    const int blk = blockIdx.x;
    if (blk < 40) {
        const int half = threadIdx.x >> 6;     // which row in this block
        const int i    = threadIdx.x & 63;     // state index within row
        const int r    = blk * 2 + half;       // global row 0..79
        const float* src = (r < NSTATE) ? (transition + r * NSTATE)
                                        : (output + (r - NSTATE) * NSTATE);
        float v = src[i];

        __shared__ float shm[4];
        __shared__ float shs[4];

        float m = v;
        #pragma unroll
        for (int d = 16; d; d >>= 1) m = fmaxf(m, __shfl_xor_sync(0xffffffffu, m, d));
        if ((threadIdx.x & 31) == 0) shm[threadIdx.x >> 5] = m;
        __syncthreads();
        m = fmaxf(shm[half * 2], shm[half * 2 + 1]);

        float e = expf(v - m);
        float s = e;
        #pragma unroll
        for (int d = 16; d; d >>= 1) s += __shfl_xor_sync(0xffffffffu, s, d);
        if ((threadIdx.x & 31) == 0) shs[threadIdx.x >> 5] = s;
        __syncthreads();
        s = shs[half * 2] + shs[half * 2 + 1];

        const float val = e / s;
        if (r < NSTATE) g_Tpack[(i >> 1) * 128 + r * 2 + (i & 1)] = val;
        else            g_Oexp[(r - NSTATE) * NSTATE + i] = val;
    } else {
        const int gw   = (blk - 40) * 4 + (threadIdx.x >> 5);
        const int lane = threadIdx.x & 31;
        if (gw >= VOCAB) return;
        const float* row = emb + gw * NSTATE;
        float s = expf(row[lane]) + expf(row[lane + 32]);
        #pragma unroll
        for (int d = 16; d; d >>= 1) s += __shfl_xor_sync(0xffffffffu, s, d);
        if (lane == 0) g_lse[gw] = logf(s);
    }
}

// ---------------------------------------------------------------------------
// Main: ONE WARP per batch element. Lane l owns states 2l and 2l+1.
// Byte-identical to the 97.0us R6 kernel EXCEPT the FMA2 emission order in
// the matvec: consumers of g.x (a0,b0) adjacent, then consumers of g.y
// (a1,b1) adjacent -> ptxas can mark the shared 64-bit operand .reuse,
// dropping the second FFMA2 of each pair from rt=3 to rt=2.
// ---------------------------------------------------------------------------
__global__ void __launch_bounds__(32) hmm_forward_kernel(
    const int*   __restrict__ sentences,
    const int*   __restrict__ length,
    const float* __restrict__ emb,
    float*       __restrict__ out)
{
    const int b    = blockIdx.x;
    const int lane = threadIdx.x;

    __shared__ __align__(16) float G[2][NSTATE];
    __shared__ int toks[MAXLEN];

    const int  L    = length[b];
    const int  Lm1  = L - 1;
    const int* sent = sentences + b * MAXLEN;

    // Stage tokens in SMEM (coalesced, 16 iterations max).
    for (int i = lane; i < L; i += 32) toks[i] = __ldg(&sent[i]);

    // Transition rows for states s0=2*lane, s1=2*lane+1:
    // TA[jv] = (Texp[s0][2jv], Texp[s0][2jv+1]), TB likewise for s1.
    // One LDG.128 per jv (16B per lane, coalesced).
    ull TA[NSTATE / 2], TB[NSTATE / 2];
    {
        const ulonglong2* Tp = reinterpret_cast<const ulonglong2*>(g_Tpack);
        #pragma unroll
        for (int jv = 0; jv < NSTATE / 2; ++jv) {
            const ulonglong2 p = __ldg(&Tp[jv * 32 + lane]);   // ull idx jv*64+2l
            TA[jv] = p.x;
            TB[jv] = p.y;
        }
    }

    // ---- t = 0 ----
    const int tok0 = __ldg(&sent[0]);
    const float2 raw0 = *reinterpret_cast<const float2*>(&emb[tok0 * NSTATE + 2 * lane]);
    *reinterpret_cast<float2*>(&G[0][2 * lane]) =
        make_float2(__expf(raw0.x), __expf(raw0.y));
    __syncwarp();   // G[0] + toks visible warp-wide

    // 3-deep emission-row prefetch (clamped indices: always valid loads).
    float2 r1 = *reinterpret_cast<const float2*>(&emb[toks[min(1, Lm1)] * NSTATE + 2 * lane]);
    float2 r2 = *reinterpret_cast<const float2*>(&emb[toks[min(2, Lm1)] * NSTATE + 2 * lane]);
    float2 r3 = *reinterpret_cast<const float2*>(&emb[toks[min(3, Lm1)] * NSTATE + 2 * lane]);

    float off = 0.f;
    int   buf = 0;

    for (int t = 1; t < L; ++t) {
        float eA = __expf(r1.x);
        float eB = __expf(r1.y);
        r1 = r2; r2 = r3;
        r3 = *reinterpret_cast<const float2*>(&emb[toks[min(t + 3, Lm1)] * NSTATE + 2 * lane]);

        if ((t & 63) == 0) {       // periodic renormalization (uniform branch)
            const float g0 = G[buf][0];
            float c;
            asm("rcp.approx.f32 %0, %1;" : "=f"(c) : "f"(g0));
            eA *= c;
            eB *= c;
            off += __logf(g0);
        }

        // Two 64-wide matvecs (states s0, s1) from shared G, packed f32x2.
        // Reuse-friendly order: both g.x consumers adjacent, then g.y.
        const ulonglong2* Gv = reinterpret_cast<const ulonglong2*>(G[buf]);
        ull a0 = 0ull, a1 = 0ull, b0 = 0ull, b1 = 0ull;
        #pragma unroll
        for (int jv = 0; jv < 16; ++jv) {
            const ulonglong2 g = Gv[jv];
            FMA2(a0, TA[2 * jv + 0], g.x, a0);
            FMA2(b0, TB[2 * jv + 0], g.x, b0);
            FMA2(a1, TA[2 * jv + 1], g.y, a1);
            FMA2(b1, TB[2 * jv + 1], g.y, b1);
        }
        ull as, bs;
        ADD2(as, a0, a1);
        ADD2(bs, b0, b1);
        float alo, ahi, blo, bhi;
        asm("mov.b64 {%0, %1}, %2;" : "=f"(alo), "=f"(ahi) : "l"(as));
        asm("mov.b64 {%0, %1}, %2;" : "=f"(blo), "=f"(bhi) : "l"(bs));
        const float GnA = (alo + ahi) * eA;
        const float GnB = (blo + bhi) * eB;

        buf ^= 1;
        *reinterpret_cast<float2*>(&G[buf][2 * lane]) = make_float2(GnA, GnB);
        __syncwarp();
    }

    // ---- emission-normalizer sum S = sum_{t<L} lse[tok_t] ----
    float S = 0.f;
    for (int i = lane; i < L; i += 32) S += __ldg(&g_lse[toks[i]]);
    #pragma unroll
    for (int d = 16; d; d >>= 1) S += __shfl_xor_sync(0xffffffffu, S, d);

    // ---- readout: lanes 0..15 each compute one label ----
    if (lane < NLABEL) {
        const float* O  = g_Oexp + lane * NSTATE;
        const float* Gf = G[buf];
        float a0 = 0.f, a1 = 0.f, a2 = 0.f, a3 = 0.f;
        #pragma unroll
        for (int j4 = 0; j4 < NSTATE / 4; ++j4) {
            a0 = fmaf(__ldg(&O[4 * j4 + 0]), Gf[4 * j4 + 0], a0);
            a1 = fmaf(__ldg(&O[4 * j4 + 1]), Gf[4 * j4 + 1], a1);
            a2 = fmaf(__ldg(&O[4 * j4 + 2]), Gf[4 * j4 + 2], a2);
            a3 = fmaf(__ldg(&O[4 * j4 + 3]), Gf[4 * j4 + 3], a3);
        }
        out[b * NLABEL + lane] = __logf((a0 + a1) + (a2 + a3)) + off - S;
    }
}

// ---------------------------------------------------------------------------
extern "C" void kernel_launch(void* const* d_in, const int* in_sizes, int n_in,
                              void* d_out, int out_size) {
    const int*   sentences  = nullptr;
    const int*   length     = nullptr;
    const float* emb        = nullptr;
    const float* transition = nullptr;
    const float* output     = nullptr;

    for (int i = 0; i < n_in; ++i) {
        switch (in_sizes[i]) {
            case BATCH * MAXLEN:   sentences  = (const int*)  d_in[i]; break;
            case BATCH:            length     = (const int*)  d_in[i]; break;
            case VOCAB * NSTATE:   emb        = (const float*)d_in[i]; break;
            case NSTATE * NSTATE:  transition = (const float*)d_in[i]; break;
            case NLABEL * NSTATE:  output     = (const float*)d_in[i]; break;
            default: break;
        }
    }

    prep_all_kernel<<<40 + VOCAB / 4, 128>>>(transition, output, emb);
    hmm_forward_kernel<<<BATCH, 32>>>(sentences, length, emb, (float*)d_out);
}